// round 17
// baseline (speedup 1.0000x reference)
#include <cuda_runtime.h>
#include <cuda_fp16.h>
#include <math.h>
#include <stdint.h>

// ---------------- problem constants ----------------
static const int B_  = 8;
static const int S_  = 256;
static const int G_  = 2048;
static const int L_  = 68;
static const int DM  = 512;
static const int NH  = 8;
static const int DH  = 64;
static const int DFF = 2048;
static const int NL  = 6;
static const int MAXE = 512;

// weight offsets in the packed fp16 weight buffer (all divisible by 8)
static const size_t OFF_FC = 0;
static const size_t OFF_IP = 2228224;
static const size_t OFF_OP = 6946816;
static const size_t OFF_F1 = 8519680;
static const size_t OFF_F2 = 14811136;
static const size_t W_TOT  = 21102592;

// ---------------- scratch (static device memory) ----------------
__device__ __half w_f [W_TOT];
__device__ __half gh_f[G_ * L_ * 64];
__device__ __half gx_f[G_ * DM];
__device__ __half at_f[G_ * DM];
__device__ __half ff_f[G_ * DFF];
__device__ __half qk_f[G_ * 3 * DM];
__device__ float g_x   [G_ * DM];
__device__ float g_proj[G_ * DM];

// =====================================================================
// merged fp32 -> fp16 weight convert, vectorized by 8
// =====================================================================
__global__ __launch_bounds__(256) void cvt_all(
    const float* __restrict__ s_fc, const float* __restrict__ s_ip,
    const float* __restrict__ s_op, const float* __restrict__ s_f1,
    const float* __restrict__ s_f2, __half* __restrict__ dst)
{
    const size_t NV = W_TOT / 8;
    size_t i = (size_t)blockIdx.x * blockDim.x + threadIdx.x;
    size_t stride = (size_t)gridDim.x * blockDim.x;
    for (; i < NV; i += stride) {
        size_t e = i * 8;
        const float* src;
        if      (e < OFF_IP) src = s_fc + e;
        else if (e < OFF_OP) src = s_ip + (e - OFF_IP);
        else if (e < OFF_F1) src = s_op + (e - OFF_OP);
        else if (e < OFF_F2) src = s_f1 + (e - OFF_F1);
        else                 src = s_f2 + (e - OFF_F2);
        float4 a = *(const float4*)(src);
        float4 b = *(const float4*)(src + 4);
        __half2 h[4];
        h[0].x = __float2half(a.x); h[0].y = __float2half(a.y);
        h[1].x = __float2half(a.z); h[1].y = __float2half(a.w);
        h[2].x = __float2half(b.x); h[2].y = __float2half(b.y);
        h[3].x = __float2half(b.z); h[3].y = __float2half(b.w);
        *(uint4*)(dst + e) = *(uint4*)h;
    }
}

// =====================================================================
// GAT: both layers fused, one block per graph; writes fp16
// =====================================================================
__global__ __launch_bounds__(128) void gat_kernel(
    const float* __restrict__ lm, const int* __restrict__ ei, int E,
    const float* __restrict__ w1, const float* __restrict__ as1,
    const float* __restrict__ ad1, const float* __restrict__ b1,
    const float* __restrict__ w2, const float* __restrict__ as2,
    const float* __restrict__ ad2, const float* __restrict__ b2,
    __half* __restrict__ out)
{
    __shared__ float h1[L_ * 16];
    __shared__ float x2[L_ * 16];
    __shared__ float h2[L_ * 64];
    __shared__ float sa[L_], sd[L_];
    __shared__ float ee[MAXE];
    __shared__ int   ssrc[MAXE], sdst[MAXE];

    const int g   = blockIdx.x;
    const int tid = threadIdx.x;
    const float* x = lm + (size_t)g * L_ * 2;

    for (int j = tid; j < E; j += blockDim.x) { ssrc[j] = ei[j]; sdst[j] = ei[E + j]; }

    for (int i = tid; i < L_ * 16; i += blockDim.x) {
        int l = i >> 4, f = i & 15;
        h1[i] = w1[f * 2 + 0] * x[l * 2 + 0] + w1[f * 2 + 1] * x[l * 2 + 1];
    }
    __syncthreads();
    if (tid < L_) {
        float a = 0.f, d = 0.f;
        #pragma unroll
        for (int f = 0; f < 16; f++) { a += h1[tid * 16 + f] * as1[f]; d += h1[tid * 16 + f] * ad1[f]; }
        sa[tid] = a; sd[tid] = d;
    }
    __syncthreads();
    for (int j = tid; j < E; j += blockDim.x) {
        float v = sa[ssrc[j]] + sd[sdst[j]];
        ee[j] = v > 0.f ? v : 0.2f * v;
    }
    __syncthreads();
    if (tid < L_) {
        float m = -1e30f;
        for (int j = 0; j < E; j++) if (sdst[j] == tid) m = fmaxf(m, ee[j]);
        float s = 0.f;
        float acc[16];
        #pragma unroll
        for (int f = 0; f < 16; f++) acc[f] = 0.f;
        for (int j = 0; j < E; j++) if (sdst[j] == tid) {
            float w = expf(ee[j] - m); s += w;
            const float* hs = &h1[ssrc[j] * 16];
            #pragma unroll
            for (int f = 0; f < 16; f++) acc[f] += w * hs[f];
        }
        float inv = 1.f / s;
        #pragma unroll
        for (int f = 0; f < 16; f++) {
            float v = acc[f] * inv + b1[f];
            x2[tid * 16 + f] = v > 0.f ? v : 0.f;
        }
    }
    __syncthreads();

    for (int i = tid; i < L_ * 64; i += blockDim.x) {
        int l = i >> 6, f = i & 63;
        float a = 0.f;
        const float* xr = &x2[l * 16];
        const float* wr = &w2[f * 16];
        #pragma unroll
        for (int c = 0; c < 16; c++) a += xr[c] * wr[c];
        h2[i] = a;
    }
    __syncthreads();
    if (tid < L_) {
        float a = 0.f, d = 0.f;
        const float* hr = &h2[tid * 64];
        #pragma unroll
        for (int f = 0; f < 64; f++) { a += hr[f] * as2[f]; d += hr[f] * ad2[f]; }
        sa[tid] = a; sd[tid] = d;
    }
    __syncthreads();
    for (int j = tid; j < E; j += blockDim.x) {
        float v = sa[ssrc[j]] + sd[sdst[j]];
        ee[j] = v > 0.f ? v : 0.2f * v;
    }
    __syncthreads();
    if (tid < L_) {
        float m = -1e30f;
        for (int j = 0; j < E; j++) if (sdst[j] == tid) m = fmaxf(m, ee[j]);
        float s = 0.f;
        float acc[64];
        #pragma unroll
        for (int f = 0; f < 64; f++) acc[f] = 0.f;
        for (int j = 0; j < E; j++) if (sdst[j] == tid) {
            float w = expf(ee[j] - m); s += w;
            const float* hs = &h2[ssrc[j] * 64];
            #pragma unroll
            for (int f = 0; f < 64; f++) acc[f] += w * hs[f];
        }
        float inv = 1.f / s;
        __half* orow = out + (size_t)g * (L_ * 64) + tid * 64;
        #pragma unroll
        for (int f = 0; f < 64; f++) {
            float v = acc[f] * inv + b2[f];
            orow[f] = __float2half(v > 0.f ? v : 0.f);
        }
    }
}

// =====================================================================
// mma helpers (fp16)
// =====================================================================
__device__ __forceinline__ void ldsm4(uint32_t& r0, uint32_t& r1, uint32_t& r2, uint32_t& r3,
                                      const __half* p) {
    uint32_t addr = (uint32_t)__cvta_generic_to_shared(p);
    asm volatile("ldmatrix.sync.aligned.m8n8.x4.shared.b16 {%0,%1,%2,%3}, [%4];\n"
                 : "=r"(r0), "=r"(r1), "=r"(r2), "=r"(r3) : "r"(addr));
}

__device__ __forceinline__ void ldsm4t(uint32_t& r0, uint32_t& r1, uint32_t& r2, uint32_t& r3,
                                       const __half* p) {
    uint32_t addr = (uint32_t)__cvta_generic_to_shared(p);
    asm volatile("ldmatrix.sync.aligned.m8n8.x4.trans.shared.b16 {%0,%1,%2,%3}, [%4];\n"
                 : "=r"(r0), "=r"(r1), "=r"(r2), "=r"(r3) : "r"(addr));
}

__device__ __forceinline__ void mma16816(float* c, const uint32_t* a, uint32_t b0, uint32_t b1) {
    asm volatile("mma.sync.aligned.m16n8k16.row.col.f32.f16.f16.f32 "
                 "{%0,%1,%2,%3}, {%4,%5,%6,%7}, {%8,%9}, {%0,%1,%2,%3};\n"
                 : "+f"(c[0]), "+f"(c[1]), "+f"(c[2]), "+f"(c[3])
                 : "r"(a[0]), "r"(a[1]), "r"(a[2]), "r"(a[3]), "r"(b0), "r"(b1));
}

__device__ __forceinline__ void cp16(uint32_t dst, const void* src) {
    asm volatile("cp.async.ca.shared.global [%0], [%1], 16;" :: "r"(dst), "l"(src));
}

// =====================================================================
// fp16 tensor-core GEMM, 64x128 block tile, K staged by 64 (R14-proven).
// 128 threads (4 warps, 2x2), warp tile 32x64.
// flags: 1 relu, 2 +pe, 4 write fp32 C, 8 write fp16 Cf
// =====================================================================
static const int TSTR = 72;
static const int GEMM_SMEM = 2 * 192 * TSTR * 2;  // 55296 B

__global__ __launch_bounds__(128) void gemm_half(
    const __half* __restrict__ A, const __half* __restrict__ B,
    const float* __restrict__ bias, float* __restrict__ C,
    __half* __restrict__ Cf,
    int M, int N, int K, int flags, const float* __restrict__ pe)
{
    extern __shared__ __half smb[];

    const int tid  = threadIdx.x;
    const int lane = tid & 31, warp = tid >> 5;
    const int wm = warp & 1, wn = warp >> 1;
    const int bm = blockIdx.y, bn = blockIdx.x;

    const __half* Ag = A + (size_t)(bm * 64) * K;
    const __half* Bg = B + (size_t)(bn * 128) * K;

    // load: 192 rows x 64 halfs = 1536 16B-chunks; 12 per thread
    auto issue = [&](int st, int k0) {
        __half* stbase = smb + (size_t)st * 192 * TSTR;
        #pragma unroll
        for (int i = 0; i < 12; i++) {
            int cix = tid + i * 128;
            int row = cix >> 3;
            int sub = (cix & 7) * 8;
            const __half* g = (row < 64) ? (Ag + (size_t)row * K)
                                         : (Bg + (size_t)(row - 64) * K);
            cp16((uint32_t)__cvta_generic_to_shared(stbase + row * TSTR + sub),
                 g + k0 + sub);
        }
        asm volatile("cp.async.commit_group;\n");
    };

    float c[2][8][4];
    #pragma unroll
    for (int i = 0; i < 2; i++)
        #pragma unroll
        for (int j = 0; j < 8; j++)
            #pragma unroll
            for (int q = 0; q < 4; q++) c[i][j][q] = 0.f;

    issue(0, 0);
    asm volatile("cp.async.wait_group 0;\n");
    __syncthreads();

    const int KT = K >> 6;
    int cur = 0;
    for (int kt = 0; kt < KT; kt++) {
        if (kt + 1 < KT) issue(cur ^ 1, (kt + 1) * 64);

        const __half* pA = smb + (size_t)cur * 192 * TSTR;
        const __half* pB = pA + 64 * TSTR;

        #pragma unroll
        for (int kh = 0; kh < 4; kh++) {
            const int r  = lane & 15;
            const int cc = kh * 16 + ((lane >> 4) << 3);
            uint32_t ah[2][4], bh[4][4];
            #pragma unroll
            for (int mt = 0; mt < 2; mt++) {
                int row = wm * 32 + mt * 16 + r;
                ldsm4(ah[mt][0], ah[mt][1], ah[mt][2], ah[mt][3], pA + row * TSTR + cc);
            }
            #pragma unroll
            for (int j = 0; j < 4; j++) {
                int row = wn * 64 + j * 16 + r;
                ldsm4(bh[j][0], bh[j][1], bh[j][2], bh[j][3], pB + row * TSTR + cc);
            }
            #pragma unroll
            for (int mt = 0; mt < 2; mt++) {
                #pragma unroll
                for (int nt = 0; nt < 8; nt++) {
                    const int j = nt >> 1, s = nt & 1;
                    mma16816(c[mt][nt], ah[mt], bh[j][s], bh[j][s + 2]);
                }
            }
        }

        if (kt + 1 < KT) {
            asm volatile("cp.async.wait_group 0;\n");
        }
        __syncthreads();
        cur ^= 1;
    }

    #pragma unroll
    for (int mt = 0; mt < 2; mt++) {
        const int mbase = bm * 64 + wm * 32 + mt * 16 + (lane >> 2);
        #pragma unroll
        for (int half_ = 0; half_ < 2; half_++) {
            const int m = mbase + half_ * 8;
            const size_t rowoff = (size_t)m * N;
            const float* perow = (flags & 2) ? (pe + (size_t)(m & (S_ - 1)) * DM) : nullptr;
            #pragma unroll
            for (int nt = 0; nt < 8; nt++) {
                const int n = bn * 128 + wn * 64 + nt * 8 + (lane & 3) * 2;
                float v0 = c[mt][nt][half_ * 2 + 0] + bias[n];
                float v1 = c[mt][nt][half_ * 2 + 1] + bias[n + 1];
                if (flags & 1) { v0 = fmaxf(v0, 0.f); v1 = fmaxf(v1, 0.f); }
                if (flags & 2) { v0 += perow[n]; v1 += perow[n + 1]; }
                if (flags & 4) {
                    float2 o; o.x = v0; o.y = v1;
                    *(float2*)(C + rowoff + n) = o;
                }
                if (flags & 8) {
                    __half2 hh; hh.x = __float2half(v0); hh.y = __float2half(v1);
                    *(__half2*)(Cf + rowoff + n) = hh;
                }
            }
        }
    }
}

// =====================================================================
// fp16 tensor-core attention: block per (b, h, q-chunk 32), 8 warps.
// Register-resident softmax; smem 96 KB -> 2 blocks/SM.
// =====================================================================
static const int KSTR = 72;
static const int SSTR = 264;
static const int OF_K  = 0;
static const int OF_V  = OF_K + 256 * KSTR * 2;
static const int OF_Q  = OF_V + 256 * KSTR * 2;
static const int OF_S2 = OF_Q + 32 * KSTR * 2;
static const int OF_RM = OF_S2 + 32 * SSTR * 2;
static const int OF_RS = OF_RM + 32 * 4 * 4;
static const int ATTN_SMEM = OF_RS + 32 * 4 * 4;     // 96256

__global__ __launch_bounds__(256) void attn_mma(
    const __half* __restrict__ qkv, __half* __restrict__ out)
{
    extern __shared__ __align__(16) char smc[];
    __half* Ks = (__half*)(smc + OF_K);
    __half* Vs = (__half*)(smc + OF_V);
    __half* Qs = (__half*)(smc + OF_Q);
    __half* S2 = (__half*)(smc + OF_S2);
    float (*Pmax)[4] = (float (*)[4])(smc + OF_RM);
    float (*Psum)[4] = (float (*)[4])(smc + OF_RS);

    const int bh  = blockIdx.x;
    const int b   = bh >> 3, hd = bh & 7;
    const int q0  = blockIdx.y * 32;
    const int tid = threadIdx.x;
    const int lane = tid & 31, warp = tid >> 5;

    const size_t rowK = (size_t)b * S_ * (3 * DM) + hd * DH;
    {
        for (int i = tid; i < 256 * 8; i += 256) {
            int r = i >> 3, cc = (i & 7) * 8;
            size_t g = rowK + (size_t)r * (3 * DM);
            *(uint4*)&Ks[r * KSTR + cc] = *(const uint4*)(qkv + g + DM + cc);
            *(uint4*)&Vs[r * KSTR + cc] = *(const uint4*)(qkv + g + 2 * DM + cc);
        }
        for (int i = tid; i < 32 * 8; i += 256) {
            int r = i >> 3, cc = (i & 7) * 8;
            size_t g = rowK + (size_t)(q0 + r) * (3 * DM);
            *(uint4*)&Qs[r * KSTR + cc] = *(const uint4*)(qkv + g + cc);
        }
    }
    __syncthreads();

    const int wm = warp & 1, wn = warp >> 1;

    float c[8][4];
    #pragma unroll
    for (int t = 0; t < 8; t++)
        #pragma unroll
        for (int q = 0; q < 4; q++) c[t][q] = 0.f;
    {
        const int r  = lane & 15;
        const int c8 = (lane >> 4) << 3;
        #pragma unroll
        for (int k0 = 0; k0 < 64; k0 += 16) {
            uint32_t aq[4];
            ldsm4(aq[0], aq[1], aq[2], aq[3], Qs + (wm * 16 + r) * KSTR + k0 + c8);
            #pragma unroll
            for (int j = 0; j < 4; j++) {
                uint32_t bk[4];
                const int key = wn * 64 + j * 16 + r;
                ldsm4(bk[0], bk[1], bk[2], bk[3], Ks + key * KSTR + k0 + c8);
                #pragma unroll
                for (int s = 0; s < 2; s++)
                    mma16816(c[2 * j + s], aq, bk[s], bk[s + 2]);
            }
        }
        #pragma unroll
        for (int t = 0; t < 8; t++)
            #pragma unroll
            for (int q = 0; q < 4; q++) c[t][q] *= 0.125f;
    }

    const int r0 = wm * 16 + (lane >> 2);
    {
        float mx0 = -1e30f, mx1 = -1e30f;
        #pragma unroll
        for (int t = 0; t < 8; t++) {
            mx0 = fmaxf(mx0, fmaxf(c[t][0], c[t][1]));
            mx1 = fmaxf(mx1, fmaxf(c[t][2], c[t][3]));
        }
        #pragma unroll
        for (int off = 1; off <= 2; off <<= 1) {
            mx0 = fmaxf(mx0, __shfl_xor_sync(0xffffffffu, mx0, off));
            mx1 = fmaxf(mx1, __shfl_xor_sync(0xffffffffu, mx1, off));
        }
        if ((lane & 3) == 0) { Pmax[r0][wn] = mx0; Pmax[r0 + 8][wn] = mx1; }
        __syncthreads();
        float m0 = fmaxf(fmaxf(Pmax[r0][0], Pmax[r0][1]), fmaxf(Pmax[r0][2], Pmax[r0][3]));
        float m1 = fmaxf(fmaxf(Pmax[r0 + 8][0], Pmax[r0 + 8][1]),
                         fmaxf(Pmax[r0 + 8][2], Pmax[r0 + 8][3]));
        float s0 = 0.f, s1 = 0.f;
        #pragma unroll
        for (int t = 0; t < 8; t++) {
            c[t][0] = expf(c[t][0] - m0); c[t][1] = expf(c[t][1] - m0);
            s0 += c[t][0] + c[t][1];
            c[t][2] = expf(c[t][2] - m1); c[t][3] = expf(c[t][3] - m1);
            s1 += c[t][2] + c[t][3];
        }
        #pragma unroll
        for (int off = 1; off <= 2; off <<= 1) {
            s0 += __shfl_xor_sync(0xffffffffu, s0, off);
            s1 += __shfl_xor_sync(0xffffffffu, s1, off);
        }
        if ((lane & 3) == 0) { Psum[r0][wn] = s0; Psum[r0 + 8][wn] = s1; }
        __syncthreads();
        float inv0 = 1.f / (Psum[r0][0] + Psum[r0][1] + Psum[r0][2] + Psum[r0][3]);
        float inv1 = 1.f / (Psum[r0 + 8][0] + Psum[r0 + 8][1] +
                            Psum[r0 + 8][2] + Psum[r0 + 8][3]);
        #pragma unroll
        for (int t = 0; t < 8; t++) {
            const int col = wn * 64 + t * 8 + (lane & 3) * 2;
            __half2 h0; h0.x = __float2half(c[t][0] * inv0); h0.y = __float2half(c[t][1] * inv0);
            __half2 h1; h1.x = __float2half(c[t][2] * inv1); h1.y = __float2half(c[t][3] * inv1);
            *(__half2*)&S2[r0 * SSTR + col]       = h0;
            *(__half2*)&S2[(r0 + 8) * SSTR + col] = h1;
        }
    }
    __syncthreads();

    {
        float o[2][4];
        #pragma unroll
        for (int t = 0; t < 2; t++)
            #pragma unroll
            for (int q = 0; q < 4; q++) o[t][q] = 0.f;

        const int r  = lane & 15;
        const int c8 = (lane >> 4) << 3;
        #pragma unroll 4
        for (int k0 = 0; k0 < 256; k0 += 16) {
            uint32_t as_[4];
            ldsm4(as_[0], as_[1], as_[2], as_[3], S2 + (wm * 16 + r) * SSTR + k0 + c8);
            uint32_t bv[4];
            ldsm4t(bv[0], bv[1], bv[2], bv[3], Vs + (k0 + r) * KSTR + wn * 16 + c8);
            #pragma unroll
            for (int t = 0; t < 2; t++)
                mma16816(o[t], as_, bv[2 * t], bv[2 * t + 1]);
        }
        const int row0 = q0 + wm * 16 + (lane >> 2);
        #pragma unroll
        for (int t = 0; t < 2; t++) {
            const int d = hd * DH + wn * 16 + t * 8 + (lane & 3) * 2;
            size_t i0 = ((size_t)b * S_ + row0) * DM + d;
            size_t i1 = ((size_t)b * S_ + row0 + 8) * DM + d;
            __half2 a; a.x = __float2half(o[t][0]); a.y = __float2half(o[t][1]);
            __half2 bb; bb.x = __float2half(o[t][2]); bb.y = __float2half(o[t][3]);
            *(__half2*)&out[i0] = a;
            *(__half2*)&out[i1] = bb;
        }
    }
}

// =====================================================================
// Residual + LayerNorm; 2 rows/block, 256 threads, float4-vectorized.
// =====================================================================
__global__ __launch_bounds__(256) void ln_kernel(
    const float* __restrict__ x, const float* __restrict__ r,
    const float* __restrict__ gam, const float* __restrict__ bet,
    float* __restrict__ out, __half* __restrict__ outh)
{
    const int grp = threadIdx.x >> 7;
    const int t   = threadIdx.x & 127;
    const int row = blockIdx.x * 2 + grp;
    const int i4  = t * 4;

    float4 xv = *(const float4*)(x + (size_t)row * DM + i4);
    float4 rv = *(const float4*)(r + (size_t)row * DM + i4);
    float v[4] = {xv.x + rv.x, xv.y + rv.y, xv.z + rv.z, xv.w + rv.w};
    float s  = v[0] + v[1] + v[2] + v[3];
    float s2 = v[0]*v[0] + v[1]*v[1] + v[2]*v[2] + v[3]*v[3];

    __shared__ float rs[2][4], rs2[2][4];
    #pragma unroll
    for (int off = 16; off; off >>= 1) {
        s  += __shfl_xor_sync(0xffffffffu, s,  off);
        s2 += __shfl_xor_sync(0xffffffffu, s2, off);
    }
    const int wig = (t >> 5);
    if ((t & 31) == 0) { rs[grp][wig] = s; rs2[grp][wig] = s2; }
    __syncthreads();
    s  = rs[grp][0] + rs[grp][1] + rs[grp][2] + rs[grp][3];
    s2 = rs2[grp][0] + rs2[grp][1] + rs2[grp][2] + rs2[grp][3];
    float mean = s * (1.f / DM);
    float var  = s2 * (1.f / DM) - mean * mean;
    float k = rsqrtf(var + 1e-5f);

    float4 gv = *(const float4*)(gam + i4);
    float4 bv = *(const float4*)(bet + i4);
    float o0 = (v[0] - mean) * k * gv.x + bv.x;
    float o1 = (v[1] - mean) * k * gv.y + bv.y;
    float o2 = (v[2] - mean) * k * gv.z + bv.z;
    float o3 = (v[3] - mean) * k * gv.w + bv.w;

    float4 ov = {o0, o1, o2, o3};
    *(float4*)(out + (size_t)row * DM + i4) = ov;
    __half2 h01; h01.x = __float2half(o0); h01.y = __float2half(o1);
    __half2 h23; h23.x = __float2half(o2); h23.y = __float2half(o3);
    __half2 hp[2] = {h01, h23};
    *(uint2*)(outh + (size_t)row * DM + i4) = *(uint2*)hp;
}

// =====================================================================
// host launcher
// =====================================================================
static void run_gemm(const __half* A, const __half* B, const float* bias,
                     float* C, __half* Cf,
                     int M, int N, int K, int flags, const float* pe) {
    dim3 grid(N / 128, M / 64);
    gemm_half<<<grid, 128, GEMM_SMEM>>>(A, B, bias, C, Cf, M, N, K, flags, pe);
}

extern "C" void kernel_launch(void* const* d_in, const int* in_sizes, int n_in,
                              void* d_out, int out_size)
{
    const float* lm    = (const float*)d_in[0];
    const int*   ei    = (const int*)  d_in[1];
    const int    E     = in_sizes[1] / 2;
    const float* g1w   = (const float*)d_in[2];
    const float* g1as  = (const float*)d_in[3];
    const float* g1ad  = (const float*)d_in[4];
    const float* g1b   = (const float*)d_in[5];
    const float* g2w   = (const float*)d_in[6];
    const float* g2as  = (const float*)d_in[7];
    const float* g2ad  = (const float*)d_in[8];
    const float* g2b   = (const float*)d_in[9];
    const float* fcw   = (const float*)d_in[10];
    const float* fcb   = (const float*)d_in[11];
    const float* pe    = (const float*)d_in[12];
    const float* ipw   = (const float*)d_in[13];
    const float* ipb   = (const float*)d_in[14];
    const float* opw   = (const float*)d_in[15];
    const float* opb   = (const float*)d_in[16];
    const float* ln1g  = (const float*)d_in[17];
    const float* ln1b  = (const float*)d_in[18];
    const float* fw1   = (const float*)d_in[19];
    const float* fb1   = (const float*)d_in[20];
    const float* fw2   = (const float*)d_in[21];
    const float* fb2   = (const float*)d_in[22];
    const float* ln2g  = (const float*)d_in[23];
    const float* ln2b  = (const float*)d_in[24];

    __half *wf, *ghf, *gxf, *atf, *fff, *qkf;
    float *gx, *gproj;
    cudaGetSymbolAddress((void**)&wf,  w_f);
    cudaGetSymbolAddress((void**)&ghf, gh_f);
    cudaGetSymbolAddress((void**)&gxf, gx_f);
    cudaGetSymbolAddress((void**)&atf, at_f);
    cudaGetSymbolAddress((void**)&fff, ff_f);
    cudaGetSymbolAddress((void**)&qkf, qk_f);
    cudaGetSymbolAddress((void**)&gx,  g_x);
    cudaGetSymbolAddress((void**)&gproj, g_proj);

    cudaFuncSetAttribute(attn_mma,  cudaFuncAttributeMaxDynamicSharedMemorySize, ATTN_SMEM);
    cudaFuncSetAttribute(gemm_half, cudaFuncAttributeMaxDynamicSharedMemorySize, GEMM_SMEM);

    // 0. weight convert (fp32 -> fp16), one merged kernel
    cvt_all<<<2048, 256>>>(fcw, ipw, opw, fw1, fw2, wf);

    // 1. GAT frontend -> fp16
    gat_kernel<<<G_, 128>>>(lm, ei, E, g1w, g1as, g1ad, g1b,
                            g2w, g2as, g2ad, g2b, ghf);

    // 2. FC + positional encoding -> fp32 gx + fp16
    run_gemm(ghf, wf + OFF_FC, fcb, gx, gxf, G_, DM, L_ * 64, 2 | 4 | 8, pe);

    // 3. transformer encoder layers
    for (int l = 0; l < NL; l++) {
        run_gemm(gxf, wf + OFF_IP + (size_t)l * 3 * DM * DM, ipb + (size_t)l * 3 * DM,
                 nullptr, qkf, G_, 3 * DM, DM, /*fp16*/ 8, nullptr);
        attn_mma<<<dim3(B_ * NH, S_ / 32), 256, ATTN_SMEM>>>(qkf, atf);
        run_gemm(atf, wf + OFF_OP + (size_t)l * DM * DM, opb + (size_t)l * DM,
                 gproj, nullptr, G_, DM, DM, 4, nullptr);
        ln_kernel<<<G_ / 2, 256>>>(gx, gproj, ln1g + (size_t)l * DM, ln1b + (size_t)l * DM,
                                   gx, gxf);

        run_gemm(gxf, wf + OFF_F1 + (size_t)l * DFF * DM, fb1 + (size_t)l * DFF,
                 nullptr, fff, G_, DFF, DM, 1 | 8, nullptr);
        run_gemm(fff, wf + OFF_F2 + (size_t)l * DM * DFF, fb2 + (size_t)l * DM,
                 gproj, nullptr, G_, DM, DFF, 4, nullptr);
        float* outp = (l == NL - 1) ? (float*)d_out : gx;
        ln_kernel<<<G_ / 2, 256>>>(gx, gproj, ln2g + (size_t)l * DM, ln2b + (size_t)l * DM,
                                   outp, gxf);
    }
    (void)n_in; (void)out_size;
}